// round 16
// baseline (speedup 1.0000x reference)
#include <cuda_runtime.h>
#include <cuda_fp16.h>
#include <cstdint>

#define NROW 8192
#define KDIM 8192
#define DIN  256
#define DOUT 256

// ---------------- scratch (static device globals; no allocations) ----------
__device__ float  g_dinv[NROW];                  // 32 KB
__device__ __half g_YT[(size_t)DIN * KDIM];      // 4 MB  Y^T[n][k] = h(d_k * X[k][n])
__device__ __half g_WT[DOUT * DIN];              // 128 KB W in half ([n][k] already)
__device__ float  g_H[(size_t)NROW * DIN];       // 8 MB  partial H (k-half 0)
__device__ float  g_H2[(size_t)NROW * DIN];      // 8 MB  partial H (k-half 1)

// ---------------- helpers ---------------------------------------------------
__device__ __forceinline__ uint32_t f2h2(float a, float b) {
    uint32_t r;
    asm("cvt.rn.f16x2.f32 %0, %2, %1;" : "=r"(r) : "f"(a), "f"(b));
    return r;   // lo half = a, hi half = b
}
__device__ __forceinline__ uint32_t smem_u32(const void* p) {
    uint32_t a;
    asm("{ .reg .u64 t; cvta.to.shared.u64 t, %1; cvt.u32.u64 %0, t; }" : "=r"(a) : "l"(p));
    return a;
}
__device__ __forceinline__ void cp16(uint32_t s, const void* g) {
    asm volatile("cp.async.cg.shared.global [%0], [%1], 16;" :: "r"(s), "l"(g));
}
__device__ __forceinline__ void cp_commit() { asm volatile("cp.async.commit_group;"); }
template <int N> __device__ __forceinline__ void cp_wait() {
    asm volatile("cp.async.wait_group %0;" :: "n"(N));
}

#define LDSM4(r, addr) \
    asm volatile("ldmatrix.sync.aligned.m8n8.x4.shared.b16 {%0,%1,%2,%3}, [%4];" \
                 : "=r"((r)[0]), "=r"((r)[1]), "=r"((r)[2]), "=r"((r)[3]) : "r"(addr))

// m16n8k16 fp16 MMA, fp32 accumulate: 2048 MACs/instruction
__device__ __forceinline__ void mma_f16(float (&c)[4], const uint32_t (&a)[4],
                                        uint32_t b0, uint32_t b1) {
    asm volatile(
        "mma.sync.aligned.m16n8k16.row.col.f32.f16.f16.f32 "
        "{%0,%1,%2,%3}, {%4,%5,%6,%7}, {%8,%9}, {%0,%1,%2,%3};\n"
        : "+f"(c[0]), "+f"(c[1]), "+f"(c[2]), "+f"(c[3])
        : "r"(a[0]), "r"(a[1]), "r"(a[2]), "r"(a[3]), "r"(b0), "r"(b1));
}

// ---------------- kernel 1: d_inv_sqrt = rsqrt(rowsum(A)) -------------------
__global__ __launch_bounds__(256) void rowsum_kernel(const float* __restrict__ A) {
    int row = blockIdx.x;
    const float4* a4 = reinterpret_cast<const float4*>(A + (size_t)row * KDIM);
    int t = threadIdx.x;
    float s = 0.0f;
#pragma unroll
    for (int j = 0; j < 8; j++) {
        float4 v = a4[t + 256 * j];
        s += (v.x + v.y) + (v.z + v.w);
    }
    __shared__ float red[256];
    red[t] = s;
    __syncthreads();
#pragma unroll
    for (int off = 128; off > 0; off >>= 1) {
        if (t < off) red[t] += red[t + off];
        __syncthreads();
    }
    if (t == 0) g_dinv[row] = rsqrtf(red[0]);
}

// ---------------- kernel 2: Y^T[n][k] = h(d_k * X[k][n]) --------------------
__global__ __launch_bounds__(256) void prepYT_kernel(const float* __restrict__ X) {
    __shared__ float ts[32][33];
    int k0 = blockIdx.x * 32, n0 = blockIdx.y * 32;
    int tx = threadIdx.x & 31, ty = threadIdx.x >> 5;   // ty 0..7
#pragma unroll
    for (int i = 0; i < 4; i++) {
        int k = k0 + ty + i * 8;
        float d = g_dinv[k];
        ts[ty + i * 8][tx] = X[(size_t)k * DIN + n0 + tx] * d;
    }
    __syncthreads();
#pragma unroll
    for (int i = 0; i < 4; i++) {
        int n = n0 + ty + i * 8;
        g_YT[(size_t)n * KDIM + k0 + tx] = __float2half_rn(ts[tx][ty + i * 8]);
    }
}

// ---------------- kernel 2b: W -> half ([n][k] row-major already) -----------
__global__ __launch_bounds__(256) void prepW_kernel(const float* __restrict__ W) {
    int idx = blockIdx.x * 256 + threadIdx.x;           // float4 index
    float4 v = reinterpret_cast<const float4*>(W)[idx];
    uint2 o;
    o.x = f2h2(v.x, v.y);
    o.y = f2h2(v.z, v.w);
    reinterpret_cast<uint2*>(g_WT)[idx] = o;
}

// ---------------- shared fp16-mma GEMM kernel -------------------------------
// C[m, 0:256] = scale(m) * A[m, kbase:kbase+nk*BK] @ B^T, B n-major half B[n][k].
// mode 0: A = adjacency, K-split 2 (blockIdx.y), C = g_H / g_H2, scale = g_dinv
// mode 1: A = g_H + g_H2 (summed on load), B = g_WT, C = out, no scale
// CTA: 256 threads, 8 warps (2m x 4n), warp tile 64x64, m16n8k16 fp16.
// BM=128, BN=256, BK=64, 3-stage cp.async ring, ldmatrix.x4, k16 double-buffer.
#define BM   128
#define BK   64
#define ARB  144                  // smem row stride bytes: 64 halfs + 16B pad
#define ASZ  (BM * ARB)           // 18432 B
#define BSZ  (256 * ARB)          // 36864 B
#define STG  (ASZ + BSZ)          // 55296 B
#define GSMEM (3 * STG)           // 165888 B
#define NT   256

// Load A chunk set for one k-tile and convert to f16x2 immediately (16 regs).
// 128 rows x 8 chunks of 8 floats = 1024 chunks; 256 threads -> 4 chunks each.
__device__ __forceinline__ void ldgA(uint32_t (&aH)[4][4],
                                     const float* Ag, const float* Ag2,
                                     size_t lda, int ctaM, int t, int k0) {
#pragma unroll
    for (int j = 0; j < 4; j++) {
        int v = t + NT * j, row = v >> 3, c = v & 7;
        const float* p = Ag + (size_t)(ctaM + row) * lda + k0 + c * 8;
        float4 x = *reinterpret_cast<const float4*>(p);
        float4 y = *reinterpret_cast<const float4*>(p + 4);
        if (Ag2) {
            const float* q = Ag2 + (size_t)(ctaM + row) * lda + k0 + c * 8;
            float4 x2 = *reinterpret_cast<const float4*>(q);
            float4 y2 = *reinterpret_cast<const float4*>(q + 4);
            x.x += x2.x; x.y += x2.y; x.z += x2.z; x.w += x2.w;
            y.x += y2.x; y.y += y2.y; y.z += y2.z; y.w += y2.w;
        }
        aH[j][0] = f2h2(x.x, x.y); aH[j][1] = f2h2(x.z, x.w);
        aH[j][2] = f2h2(y.x, y.y); aH[j][3] = f2h2(y.z, y.w);
    }
}
__device__ __forceinline__ void stsA(uint32_t abase, int t, const uint32_t (&aH)[4][4]) {
#pragma unroll
    for (int j = 0; j < 4; j++) {
        int v = t + NT * j, row = v >> 3, c = v & 7;
        uint32_t d = abase + row * ARB + c * 16;
        asm volatile("st.shared.v4.b32 [%0], {%1,%2,%3,%4};"
                     :: "r"(d), "r"(aH[j][0]), "r"(aH[j][1]), "r"(aH[j][2]), "r"(aH[j][3]));
    }
}
__device__ __forceinline__ void cpB(uint32_t bbase, const __half* Bg, size_t ldb,
                                    int t, int k0) {
#pragma unroll
    for (int j = 0; j < 8; j++) {
        int v = t + NT * j, n = v >> 3, c = v & 7;    // 256 rows x 8 chunks of 8 halfs
        cp16(bbase + n * ARB + c * 16, Bg + (size_t)n * ldb + k0 + c * 8);
    }
}

__global__ __launch_bounds__(NT, 1)
void gemm_tc(const float* __restrict__ Aext, float* __restrict__ Cext, int mode) {
    extern __shared__ char smem[];
    uint32_t sb = smem_u32(smem);

    const float* Ag;  const float* Ag2;  size_t lda;
    const __half* Bg;  size_t ldb;
    float* C;  const float* scale;  int nk, kbase;
    if (mode == 0) {
        Ag = Aext; Ag2 = nullptr; lda = KDIM; Bg = g_YT; ldb = KDIM;
        C = blockIdx.y ? g_H2 : g_H; scale = g_dinv;
        nk = (KDIM / 2) / BK; kbase = blockIdx.y * (KDIM / 2);
    } else {
        Ag = g_H; Ag2 = g_H2; lda = DIN; Bg = g_WT; ldb = DIN;
        C = Cext; scale = nullptr; nk = DIN / BK; kbase = 0;
    }

    int t = threadIdx.x, wid = t >> 5, lane = t & 31;
    int warp_m = wid >> 2, warp_n = wid & 3;    // 2 x 4
    int ctaM = blockIdx.x * BM;

    float acc[4][8][4];                         // warp tile 64x64: 4 m16 x 8 n8
#pragma unroll
    for (int mi = 0; mi < 4; mi++)
#pragma unroll
        for (int ni = 0; ni < 8; ni++)
#pragma unroll
            for (int q = 0; q < 4; q++) acc[mi][ni][q] = 0.0f;

    // per-thread ldmatrix offsets (relative to stage base)
    // A (16x16 tiles via x4): lane l -> row (l & 15), byte (l>>4)*16
    uint32_t aO = (uint32_t)((warp_m * 64 + (lane & 15)) * ARB + (lane >> 4) * 16);
    // B (two n8 frags via x4): lane l -> row (l>>4)*8 + (l&7), byte ((l>>3)&1)*16
    uint32_t brow = (uint32_t)((lane >> 4) * 8 + (lane & 7));
    uint32_t bbyte = (uint32_t)(((lane >> 3) & 1) * 16);
    uint32_t bO = (uint32_t)((warp_n * 64 + brow) * ARB + bbyte) + ASZ;

    // ---- prologue: stage tiles 0 and 1; tile 2 into regs ----
    uint32_t aH[4][4];
    ldgA(aH, Ag, Ag2, lda, ctaM, t, kbase);
    stsA(sb + 0 * STG, t, aH);
    cpB(sb + 0 * STG + ASZ, Bg, ldb, t, kbase);
    cp_commit();
    ldgA(aH, Ag, Ag2, lda, ctaM, t, kbase + BK);
    stsA(sb + 1 * STG, t, aH);
    cpB(sb + 1 * STG + ASZ, Bg, ldb, t, kbase + BK);
    cp_commit();
    ldgA(aH, Ag, Ag2, lda, ctaM, t, kbase + 2 * BK);

    // fragment double buffers (k16-level software pipeline)
    uint32_t af[2][4][4];     // [buf][mi][reg]
    uint32_t bf[2][4][4];     // [buf][nj][reg]  ([0,1]=n8 lo, [2,3]=n8 hi)

    // ---- main loop ----
    for (int kt = 0; kt < nk; kt++) {
        cp_wait<1>();
        __syncthreads();

        uint32_t base = sb + (kt % 3) * STG;
        uint32_t aAdr = base + aO;
        uint32_t bAdr = base + bO;

        // prefetch k16=0 fragments; latency hides behind staging issue below
#pragma unroll
        for (int mi = 0; mi < 4; mi++) LDSM4(af[0][mi], aAdr + mi * 16 * ARB);
#pragma unroll
        for (int nj = 0; nj < 4; nj++) LDSM4(bf[0][nj], bAdr + nj * 16 * ARB);

        // stage tile L = kt + 2
        int L = kt + 2;
        if (L < nk) {
            uint32_t stg = sb + (L % 3) * STG;
            stsA(stg, t, aH);
            if (L + 1 < nk) ldgA(aH, Ag, Ag2, lda, ctaM, t, kbase + (L + 1) * BK);
            cpB(stg + ASZ, Bg, ldb, t, kbase + L * BK);
        }
        cp_commit();   // empty group near the tail keeps wait<1> accounting uniform

        // compute: 4 k16 steps, double-buffered fragments, 32 MMAs each
#pragma unroll
        for (int k16 = 0; k16 < 4; k16++) {
            int cur = k16 & 1, nxt = cur ^ 1;
            if (k16 < 3) {
#pragma unroll
                for (int mi = 0; mi < 4; mi++)
                    LDSM4(af[nxt][mi], aAdr + mi * 16 * ARB + (k16 + 1) * 32);
#pragma unroll
                for (int nj = 0; nj < 4; nj++)
                    LDSM4(bf[nxt][nj], bAdr + nj * 16 * ARB + (k16 + 1) * 32);
            }
#pragma unroll
            for (int mi = 0; mi < 4; mi++)
#pragma unroll
                for (int nj = 0; nj < 4; nj++) {
                    mma_f16(acc[mi][2 * nj],     af[cur][mi], bf[cur][nj][0], bf[cur][nj][1]);
                    mma_f16(acc[mi][2 * nj + 1], af[cur][mi], bf[cur][nj][2], bf[cur][nj][3]);
                }
        }
    }

    // ---- epilogue: optional row scale, store ----
#pragma unroll
    for (int mi = 0; mi < 4; mi++) {
        int r = ctaM + warp_m * 64 + mi * 16 + (lane >> 2);
        float s0 = scale ? scale[r] : 1.0f;
        float s1 = scale ? scale[r + 8] : 1.0f;
#pragma unroll
        for (int ni = 0; ni < 8; ni++) {
            int col = warp_n * 64 + ni * 8 + 2 * (lane & 3);
            float2 v0 = make_float2(acc[mi][ni][0] * s0, acc[mi][ni][1] * s0);
            float2 v1 = make_float2(acc[mi][ni][2] * s1, acc[mi][ni][3] * s1);
            *reinterpret_cast<float2*>(&C[(size_t)r * DIN + col]) = v0;
            *reinterpret_cast<float2*>(&C[(size_t)(r + 8) * DIN + col]) = v1;
        }
    }
}

// ---------------- launch ----------------------------------------------------
extern "C" void kernel_launch(void* const* d_in, const int* in_sizes, int n_in,
                              void* d_out, int out_size) {
    const float* X = (const float*)d_in[0];   // [8192, 256]
    const float* A = (const float*)d_in[1];   // [8192, 8192]
    const float* W = (const float*)d_in[2];   // [256, 256]
    float* out = (float*)d_out;               // [8192, 256]

    cudaFuncSetAttribute(gemm_tc, cudaFuncAttributeMaxDynamicSharedMemorySize, GSMEM);

    rowsum_kernel<<<NROW, 256>>>(A);
    prepYT_kernel<<<dim3(KDIM / 32, DIN / 32), 256>>>(X);
    prepW_kernel<<<(DOUT * DIN / 4) / 256, 256>>>(W);
    gemm_tc<<<dim3(NROW / BM, 2), NT, GSMEM>>>(A, nullptr, 0);   // partial H halves
    gemm_tc<<<dim3(NROW / BM, 1), NT, GSMEM>>>(nullptr, out, 1); // out = (H1+H2) @ W^T
}

// round 17
// speedup vs baseline: 1.1374x; 1.1374x over previous
#include <cuda_runtime.h>
#include <cuda_fp16.h>
#include <cstdint>

#define NROW 8192
#define KDIM 8192
#define DIN  256
#define DOUT 256

// ---------------- scratch (static device globals; no allocations) ----------
__device__ float  g_dinv[NROW];                  // 32 KB
__device__ __half g_YT[(size_t)DIN * KDIM];      // 4 MB  Y^T[n][k] = h(d_k * X[k][n])
__device__ __half g_WT[DOUT * DIN];              // 128 KB W in half ([n][k] already)
__device__ float  g_H[(size_t)NROW * DIN];       // 8 MB  partial H (k-half 0)
__device__ float  g_H2[(size_t)NROW * DIN];      // 8 MB  partial H (k-half 1)

// ---------------- helpers ---------------------------------------------------
__device__ __forceinline__ uint32_t f2h2(float a, float b) {
    uint32_t r;
    asm("cvt.rn.f16x2.f32 %0, %2, %1;" : "=r"(r) : "f"(a), "f"(b));
    return r;   // lo half = a, hi half = b
}
__device__ __forceinline__ uint32_t smem_u32(const void* p) {
    uint32_t a;
    asm("{ .reg .u64 t; cvta.to.shared.u64 t, %1; cvt.u32.u64 %0, t; }" : "=r"(a) : "l"(p));
    return a;
}
__device__ __forceinline__ void cp16(uint32_t s, const void* g) {
    asm volatile("cp.async.cg.shared.global [%0], [%1], 16;" :: "r"(s), "l"(g));
}
__device__ __forceinline__ void cp_commit() { asm volatile("cp.async.commit_group;"); }
template <int N> __device__ __forceinline__ void cp_wait() {
    asm volatile("cp.async.wait_group %0;" :: "n"(N));
}

#define LDSM4(r, addr) \
    asm volatile("ldmatrix.sync.aligned.m8n8.x4.shared.b16 {%0,%1,%2,%3}, [%4];" \
                 : "=r"((r)[0]), "=r"((r)[1]), "=r"((r)[2]), "=r"((r)[3]) : "r"(addr))

// m16n8k16 fp16 MMA, fp32 accumulate: 2048 MACs/instruction
__device__ __forceinline__ void mma_f16(float (&c)[4], const uint32_t (&a)[4],
                                        uint32_t b0, uint32_t b1) {
    asm volatile(
        "mma.sync.aligned.m16n8k16.row.col.f32.f16.f16.f32 "
        "{%0,%1,%2,%3}, {%4,%5,%6,%7}, {%8,%9}, {%0,%1,%2,%3};\n"
        : "+f"(c[0]), "+f"(c[1]), "+f"(c[2]), "+f"(c[3])
        : "r"(a[0]), "r"(a[1]), "r"(a[2]), "r"(a[3]), "r"(b0), "r"(b1));
}

// ---------------- kernel 1: d_inv_sqrt = rsqrt(rowsum(A)) -------------------
__global__ __launch_bounds__(256) void rowsum_kernel(const float* __restrict__ A) {
    int row = blockIdx.x;
    const float4* a4 = reinterpret_cast<const float4*>(A + (size_t)row * KDIM);
    int t = threadIdx.x;
    float s = 0.0f;
#pragma unroll
    for (int j = 0; j < 8; j++) {
        float4 v = a4[t + 256 * j];
        s += (v.x + v.y) + (v.z + v.w);
    }
    __shared__ float red[256];
    red[t] = s;
    __syncthreads();
#pragma unroll
    for (int off = 128; off > 0; off >>= 1) {
        if (t < off) red[t] += red[t + off];
        __syncthreads();
    }
    if (t == 0) g_dinv[row] = rsqrtf(red[0]);
}

// ---------------- kernel 2: Y^T[n][k] = h(d_k * X[k][n]) --------------------
__global__ __launch_bounds__(256) void prepYT_kernel(const float* __restrict__ X) {
    __shared__ float ts[32][33];
    int k0 = blockIdx.x * 32, n0 = blockIdx.y * 32;
    int tx = threadIdx.x & 31, ty = threadIdx.x >> 5;   // ty 0..7
#pragma unroll
    for (int i = 0; i < 4; i++) {
        int k = k0 + ty + i * 8;
        float d = g_dinv[k];
        ts[ty + i * 8][tx] = X[(size_t)k * DIN + n0 + tx] * d;
    }
    __syncthreads();
#pragma unroll
    for (int i = 0; i < 4; i++) {
        int n = n0 + ty + i * 8;
        g_YT[(size_t)n * KDIM + k0 + tx] = __float2half_rn(ts[tx][ty + i * 8]);
    }
}

// ---------------- kernel 2b: W -> half ([n][k] row-major already) -----------
__global__ __launch_bounds__(256) void prepW_kernel(const float* __restrict__ W) {
    int idx = blockIdx.x * 256 + threadIdx.x;           // float4 index
    float4 v = reinterpret_cast<const float4*>(W)[idx];
    uint2 o;
    o.x = f2h2(v.x, v.y);
    o.y = f2h2(v.z, v.w);
    reinterpret_cast<uint2*>(g_WT)[idx] = o;
}

// ---------------- shared fp16-mma GEMM kernel -------------------------------
// C[m, 0:256] = scale(m) * A[m, kbase:kbase+nk*BK] @ B^T, B n-major half B[n][k].
// mode 0: A = adjacency, K-split 2 (blockIdx.y), C = g_H / g_H2, scale = g_dinv
// mode 1: A = g_H + g_H2 (summed on load), B = g_WT, C = out, no scale
// CTA: 512 threads, 16 warps (4m x 4n), warp tile 32x64, m16n8k16 fp16.
// BM=128, BN=256, BK=64, 3-stage cp.async ring, ldmatrix.x4, single-buffer frags.
#define BM   128
#define BK   64
#define ARB  144                  // smem row stride bytes: 64 halfs + 16B pad
#define ASZ  (BM * ARB)           // 18432 B
#define BSZ  (256 * ARB)          // 36864 B
#define STG  (ASZ + BSZ)          // 55296 B
#define GSMEM (3 * STG)           // 165888 B
#define NT   512

// A staging: 128 rows x 8 chunks of 8 floats = 1024 chunks; 2 per thread.
__device__ __forceinline__ void ldgA(uint32_t (&aH)[2][4],
                                     const float* Ag, const float* Ag2,
                                     size_t lda, int ctaM, int t, int k0) {
#pragma unroll
    for (int j = 0; j < 2; j++) {
        int v = t + NT * j, row = v >> 3, c = v & 7;
        const float* p = Ag + (size_t)(ctaM + row) * lda + k0 + c * 8;
        float4 x = *reinterpret_cast<const float4*>(p);
        float4 y = *reinterpret_cast<const float4*>(p + 4);
        if (Ag2) {
            const float* q = Ag2 + (size_t)(ctaM + row) * lda + k0 + c * 8;
            float4 x2 = *reinterpret_cast<const float4*>(q);
            float4 y2 = *reinterpret_cast<const float4*>(q + 4);
            x.x += x2.x; x.y += x2.y; x.z += x2.z; x.w += x2.w;
            y.x += y2.x; y.y += y2.y; y.z += y2.z; y.w += y2.w;
        }
        aH[j][0] = f2h2(x.x, x.y); aH[j][1] = f2h2(x.z, x.w);
        aH[j][2] = f2h2(y.x, y.y); aH[j][3] = f2h2(y.z, y.w);
    }
}
__device__ __forceinline__ void stsA(uint32_t abase, int t, const uint32_t (&aH)[2][4]) {
#pragma unroll
    for (int j = 0; j < 2; j++) {
        int v = t + NT * j, row = v >> 3, c = v & 7;
        uint32_t d = abase + row * ARB + c * 16;
        asm volatile("st.shared.v4.b32 [%0], {%1,%2,%3,%4};"
                     :: "r"(d), "r"(aH[j][0]), "r"(aH[j][1]), "r"(aH[j][2]), "r"(aH[j][3]));
    }
}
__device__ __forceinline__ void cpB(uint32_t bbase, const __half* Bg, size_t ldb,
                                    int t, int k0) {
#pragma unroll
    for (int j = 0; j < 4; j++) {
        int v = t + NT * j, n = v >> 3, c = v & 7;    // 256 rows x 8 chunks of 8 halfs
        cp16(bbase + n * ARB + c * 16, Bg + (size_t)n * ldb + k0 + c * 8);
    }
}

__global__ __launch_bounds__(NT, 1)
void gemm_tc(const float* __restrict__ Aext, float* __restrict__ Cext, int mode) {
    extern __shared__ char smem[];
    uint32_t sb = smem_u32(smem);

    const float* Ag;  const float* Ag2;  size_t lda;
    const __half* Bg;  size_t ldb;
    float* C;  const float* scale;  int nk, kbase;
    if (mode == 0) {
        Ag = Aext; Ag2 = nullptr; lda = KDIM; Bg = g_YT; ldb = KDIM;
        C = blockIdx.y ? g_H2 : g_H; scale = g_dinv;
        nk = (KDIM / 2) / BK; kbase = blockIdx.y * (KDIM / 2);
    } else {
        Ag = g_H; Ag2 = g_H2; lda = DIN; Bg = g_WT; ldb = DIN;
        C = Cext; scale = nullptr; nk = DIN / BK; kbase = 0;
    }

    int t = threadIdx.x, wid = t >> 5, lane = t & 31;
    int warp_m = wid >> 2, warp_n = wid & 3;    // 4 x 4
    int ctaM = blockIdx.x * BM;

    float acc[2][8][4];                         // warp tile 32x64: 2 m16 x 8 n8
#pragma unroll
    for (int mi = 0; mi < 2; mi++)
#pragma unroll
        for (int ni = 0; ni < 8; ni++)
#pragma unroll
            for (int q = 0; q < 4; q++) acc[mi][ni][q] = 0.0f;

    // per-thread ldmatrix offsets (relative to stage base)
    // A (16x16 tiles via x4): lane l -> row (l & 15), byte (l>>4)*16
    uint32_t aO = (uint32_t)((warp_m * 32 + (lane & 15)) * ARB + (lane >> 4) * 16);
    // B (two n8 frags via x4): lane l -> row (l>>4)*8 + (l&7), byte ((l>>3)&1)*16
    uint32_t brow = (uint32_t)((lane >> 4) * 8 + (lane & 7));
    uint32_t bbyte = (uint32_t)(((lane >> 3) & 1) * 16);
    uint32_t bO = (uint32_t)((warp_n * 64 + brow) * ARB + bbyte) + ASZ;

    // ---- prologue: stage tiles 0 and 1; tile 2 into regs ----
    uint32_t aH[2][4];
    ldgA(aH, Ag, Ag2, lda, ctaM, t, kbase);
    stsA(sb + 0 * STG, t, aH);
    cpB(sb + 0 * STG + ASZ, Bg, ldb, t, kbase);
    cp_commit();
    ldgA(aH, Ag, Ag2, lda, ctaM, t, kbase + BK);
    stsA(sb + 1 * STG, t, aH);
    cpB(sb + 1 * STG + ASZ, Bg, ldb, t, kbase + BK);
    cp_commit();
    ldgA(aH, Ag, Ag2, lda, ctaM, t, kbase + 2 * BK);

    // single-buffer fragments (WLP via 4 warps/SMSP hides LDS latency)
    uint32_t af[2][4];        // [mi][reg]
    uint32_t bf[4][4];        // [nj][reg]   ([0,1]=n8 lo, [2,3]=n8 hi)

    // ---- main loop ----
    for (int kt = 0; kt < nk; kt++) {
        cp_wait<1>();
        __syncthreads();

        uint32_t base = sb + (kt % 3) * STG;
        uint32_t aAdr = base + aO;
        uint32_t bAdr = base + bO;

        // prefetch k16=0 fragments; latency hides behind staging issue below
        LDSM4(af[0], aAdr);
        LDSM4(af[1], aAdr + 16 * ARB);
#pragma unroll
        for (int nj = 0; nj < 4; nj++) LDSM4(bf[nj], bAdr + nj * 16 * ARB);

        // stage tile L = kt + 2
        int L = kt + 2;
        if (L < nk) {
            uint32_t stg = sb + (L % 3) * STG;
            stsA(stg, t, aH);
            if (L + 1 < nk) ldgA(aH, Ag, Ag2, lda, ctaM, t, kbase + (L + 1) * BK);
            cpB(stg + ASZ, Bg, ldb, t, kbase + L * BK);
        }
        cp_commit();   // empty group near the tail keeps wait<1> accounting uniform

        // compute: 4 k16 steps, 16 MMAs each; frags reloaded per step
#pragma unroll
        for (int k16 = 0; k16 < 4; k16++) {
#pragma unroll
            for (int mi = 0; mi < 2; mi++)
#pragma unroll
                for (int nj = 0; nj < 4; nj++) {
                    mma_f16(acc[mi][2 * nj],     af[mi], bf[nj][0], bf[nj][1]);
                    mma_f16(acc[mi][2 * nj + 1], af[mi], bf[nj][2], bf[nj][3]);
                }
            if (k16 < 3) {
                LDSM4(af[0], aAdr + (k16 + 1) * 32);
                LDSM4(af[1], aAdr + 16 * ARB + (k16 + 1) * 32);
#pragma unroll
                for (int nj = 0; nj < 4; nj++)
                    LDSM4(bf[nj], bAdr + nj * 16 * ARB + (k16 + 1) * 32);
            }
        }
    }

    // ---- epilogue: optional row scale, store ----
#pragma unroll
    for (int mi = 0; mi < 2; mi++) {
        int r = ctaM + warp_m * 32 + mi * 16 + (lane >> 2);
        float s0 = scale ? scale[r] : 1.0f;
        float s1 = scale ? scale[r + 8] : 1.0f;
#pragma unroll
        for (int ni = 0; ni < 8; ni++) {
            int col = warp_n * 64 + ni * 8 + 2 * (lane & 3);
            float2 v0 = make_float2(acc[mi][ni][0] * s0, acc[mi][ni][1] * s0);
            float2 v1 = make_float2(acc[mi][ni][2] * s1, acc[mi][ni][3] * s1);
            *reinterpret_cast<float2*>(&C[(size_t)r * DIN + col]) = v0;
            *reinterpret_cast<float2*>(&C[(size_t)(r + 8) * DIN + col]) = v1;
        }
    }
}

// ---------------- launch ----------------------------------------------------
extern "C" void kernel_launch(void* const* d_in, const int* in_sizes, int n_in,
                              void* d_out, int out_size) {
    const float* X = (const float*)d_in[0];   // [8192, 256]
    const float* A = (const float*)d_in[1];   // [8192, 8192]
    const float* W = (const float*)d_in[2];   // [256, 256]
    float* out = (float*)d_out;               // [8192, 256]

    cudaFuncSetAttribute(gemm_tc, cudaFuncAttributeMaxDynamicSharedMemorySize, GSMEM);

    rowsum_kernel<<<NROW, 256>>>(A);
    prepYT_kernel<<<dim3(KDIM / 32, DIN / 32), 256>>>(X);
    prepW_kernel<<<(DOUT * DIN / 4) / 256, 256>>>(W);
    gemm_tc<<<dim3(NROW / BM, 2), NT, GSMEM>>>(A, nullptr, 0);   // partial H halves
    gemm_tc<<<dim3(NROW / BM, 1), NT, GSMEM>>>(nullptr, out, 1); // out = (H1+H2) @ W^T
}